// round 1
// baseline (speedup 1.0000x reference)
#include <cuda_runtime.h>

#define N_NODES 50000
#define N_EDGES 800000
#define HEADS   3
#define HF      64            // H_FEATS
#define HFO     (HEADS*HF)    // 192
#define NCLS    2
#define HFO3    (HEADS*NCLS)  // 6
#define NEG     0.2f

// ---------------- scratch (device globals; no allocation allowed) ----------
__device__ __align__(16) float    g_feat[N_NODES * HFO];   // per-layer feat [N,H,Fo]
__device__ __align__(16) float    g_rst [N_NODES * HFO];   // aggregation target
__device__ float    g_el  [N_NODES * HEADS];
__device__ float    g_er  [N_NODES * HEADS];
__device__ unsigned g_menc[N_NODES * HEADS];               // encoded max
__device__ float    g_s   [N_NODES * HEADS];               // softmax denom
__device__ float    g_ex  [N_EDGES * HEADS];               // exp(e - m)
__device__ float    g_h   [N_NODES * HF];                  // inter-layer node feats

// ---------------- helpers ---------------------------------------------------
__device__ __forceinline__ unsigned fenc(float f) {
    unsigned u = __float_as_uint(f);
    return (u & 0x80000000u) ? ~u : (u | 0x80000000u);   // order-preserving
}
__device__ __forceinline__ float fdec(unsigned k) {
    return (k & 0x80000000u) ? __uint_as_float(k ^ 0x80000000u)
                             : __uint_as_float(~k);
}
__device__ __forceinline__ float lrelu(float v) { return v > 0.f ? v : NEG * v; }

// ---------------- init ------------------------------------------------------
__global__ void init_ms(unsigned* menc, float* s, int n) {
    int i = blockIdx.x * blockDim.x + threadIdx.x;
    if (i < n) { menc[i] = 0u; s[i] = 0.f; }   // key 0 < enc(any finite float)
}
__global__ void fill_zero(float* p, int n) {
    int i = blockIdx.x * blockDim.x + threadIdx.x;
    if (i < n) p[i] = 0.f;
}

// ---------------- GEMM: feat = x @ W  (HFo = 192 path) ----------------------
// blockDim = 192 (one thread per output column), 8 nodes per block.
template <int FIN>
__global__ void gemm_big(const float* __restrict__ x,
                         const float* __restrict__ W,
                         float* __restrict__ feat) {
    __shared__ float xs[8 * FIN];
    const int t  = threadIdx.x;            // output column 0..191
    const int n0 = blockIdx.x * 8;
    for (int i = t; i < 8 * FIN; i += 192) {
        int node = n0 + i / FIN;
        xs[i] = (node < N_NODES) ? x[node * FIN + i % FIN] : 0.f;
    }
    __syncthreads();
    float acc[8];
#pragma unroll
    for (int i = 0; i < 8; i++) acc[i] = 0.f;
    for (int k = 0; k < FIN; k++) {
        float wv = __ldg(&W[k * HFO + t]);
#pragma unroll
        for (int i = 0; i < 8; i++) acc[i] += xs[i * FIN + k] * wv;
    }
#pragma unroll
    for (int i = 0; i < 8; i++) {
        int node = n0 + i;
        if (node < N_NODES) feat[node * HFO + t] = acc[i];
    }
}

// ---------------- GEMM: small output (layer 3, HFo = 6) ---------------------
__global__ void gemm_small(const float* __restrict__ x,
                           const float* __restrict__ W,
                           float* __restrict__ feat,
                           int Fin, int HFo, int total) {
    int idx = blockIdx.x * blockDim.x + threadIdx.x;
    if (idx >= total) return;
    int n = idx / HFo, c = idx % HFo;
    float acc = 0.f;
    const float* xr = x + n * Fin;
    for (int k = 0; k < Fin; k++) acc += xr[k] * __ldg(&W[k * HFo + c]);
    feat[idx] = acc;
}

// ---------------- el/er = <feat, attn_{l,r}> per (node, head) ---------------
__global__ void attn_dots(const float* __restrict__ feat,
                          const float* __restrict__ al,
                          const float* __restrict__ ar,
                          float* __restrict__ el, float* __restrict__ er,
                          int Fo) {
    int idx = blockIdx.x * blockDim.x + threadIdx.x;   // n*HEADS + h
    if (idx >= N_NODES * HEADS) return;
    int n = idx / HEADS, h = idx % HEADS;
    const float* fp  = feat + (n * HEADS + h) * Fo;
    const float* alp = al + h * Fo;
    const float* arp = ar + h * Fo;
    float sl = 0.f, sr = 0.f;
    for (int f = 0; f < Fo; f++) {
        float v = fp[f];
        sl += v * __ldg(&alp[f]);
        sr += v * __ldg(&arp[f]);
    }
    el[idx] = sl;
    er[idx] = sr;
}

// ---------------- edge pass 1: segment max ----------------------------------
__global__ void edge_max(const int* __restrict__ src, const int* __restrict__ dst,
                         const float* __restrict__ el, const float* __restrict__ er,
                         unsigned* __restrict__ menc) {
    int e = blockIdx.x * blockDim.x + threadIdx.x;
    if (e >= N_EDGES) return;
    int s = src[e], d = dst[e];
#pragma unroll
    for (int h = 0; h < HEADS; h++) {
        float v = lrelu(el[s * HEADS + h] + er[d * HEADS + h]);
        atomicMax(&menc[d * HEADS + h], fenc(v));
    }
}

// ---------------- edge pass 2: exp + segment sum -----------------------------
__global__ void edge_exp(const int* __restrict__ src, const int* __restrict__ dst,
                         const float* __restrict__ el, const float* __restrict__ er,
                         const unsigned* __restrict__ menc,
                         float* __restrict__ ex, float* __restrict__ ssum) {
    int e = blockIdx.x * blockDim.x + threadIdx.x;
    if (e >= N_EDGES) return;
    int s = src[e], d = dst[e];
#pragma unroll
    for (int h = 0; h < HEADS; h++) {
        float v = lrelu(el[s * HEADS + h] + er[d * HEADS + h]);
        float m = fdec(menc[d * HEADS + h]);
        float x = __expf(v - m);
        ex[e * HEADS + h] = x;
        atomicAdd(&ssum[d * HEADS + h], x);
    }
}

// ---------------- edge pass 3: weighted aggregation (Fo = 64) ----------------
// one thread per (edge, head); 16x float4 gather + red.global.add.v4.f32
__global__ void edge_agg_big(const int* __restrict__ src, const int* __restrict__ dst,
                             const float* __restrict__ ex, const float* __restrict__ ssum,
                             const float* __restrict__ feat, float* __restrict__ rst) {
    int idx = blockIdx.x * blockDim.x + threadIdx.x;   // e*HEADS + h
    if (idx >= N_EDGES * HEADS) return;
    int e = idx / HEADS, h = idx % HEADS;
    int s = src[e], d = dst[e];
    float alpha = ex[idx] / ssum[d * HEADS + h];
    const float4* fp = reinterpret_cast<const float4*>(feat + s * HFO + h * HF);
    float* rp = rst + d * HFO + h * HF;
#pragma unroll
    for (int i = 0; i < HF / 4; i++) {
        float4 v = __ldg(fp + i);
        float a = v.x * alpha, b = v.y * alpha, c = v.z * alpha, w = v.w * alpha;
        asm volatile("red.global.add.v4.f32 [%0], {%1,%2,%3,%4};"
                     :: "l"(rp + i * 4), "f"(a), "f"(b), "f"(c), "f"(w)
                     : "memory");
    }
}

// ---------------- edge pass 3: weighted aggregation (Fo = 2, layer 3) --------
__global__ void edge_agg_small(const int* __restrict__ src, const int* __restrict__ dst,
                               const float* __restrict__ ex, const float* __restrict__ ssum,
                               const float* __restrict__ feat, float* __restrict__ rst) {
    int e = blockIdx.x * blockDim.x + threadIdx.x;
    if (e >= N_EDGES) return;
    int s = src[e], d = dst[e];
#pragma unroll
    for (int h = 0; h < HEADS; h++) {
        float alpha = ex[e * HEADS + h] / ssum[d * HEADS + h];
        float v0 = feat[s * HFO3 + h * NCLS + 0];
        float v1 = feat[s * HFO3 + h * NCLS + 1];
        atomicAdd(&rst[d * HFO3 + h * NCLS + 0], alpha * v0);
        atomicAdd(&rst[d * HFO3 + h * NCLS + 1], alpha * v1);
    }
}

// ---------------- head-sum + bias -------------------------------------------
__global__ void head_sum(const float* __restrict__ rst, const float* __restrict__ b,
                         float* __restrict__ out, int Fo, int total) {
    int idx = blockIdx.x * blockDim.x + threadIdx.x;   // n*Fo + fo
    if (idx >= total) return;
    int n = idx / Fo, fo = idx % Fo;
    float acc = 0.f;
#pragma unroll
    for (int h = 0; h < HEADS; h++)
        acc += rst[(n * HEADS + h) * Fo + fo] + __ldg(&b[h * Fo + fo]);
    out[idx] = acc;
}

// ---------------- host driver ------------------------------------------------
static inline int cdiv(int a, int b) { return (a + b - 1) / b; }

extern "C" void kernel_launch(void* const* d_in, const int* in_sizes, int n_in,
                              void* d_out, int out_size) {
    const float* feats = (const float*)d_in[0];
    const int*   src   = (const int*)  d_in[1];
    const int*   dst   = (const int*)  d_in[2];
    const float* W1 = (const float*)d_in[3],  *al1 = (const float*)d_in[4];
    const float* ar1= (const float*)d_in[5],  *b1  = (const float*)d_in[6];
    const float* W2 = (const float*)d_in[7],  *al2 = (const float*)d_in[8];
    const float* ar2= (const float*)d_in[9],  *b2  = (const float*)d_in[10];
    const float* W3 = (const float*)d_in[11], *al3 = (const float*)d_in[12];
    const float* ar3= (const float*)d_in[13], *b3  = (const float*)d_in[14];
    float* out = (float*)d_out;

    float *feat, *rst, *el, *er, *s, *ex, *h;
    unsigned* menc;
    cudaGetSymbolAddress((void**)&feat, g_feat);
    cudaGetSymbolAddress((void**)&rst,  g_rst);
    cudaGetSymbolAddress((void**)&el,   g_el);
    cudaGetSymbolAddress((void**)&er,   g_er);
    cudaGetSymbolAddress((void**)&menc, g_menc);
    cudaGetSymbolAddress((void**)&s,    g_s);
    cudaGetSymbolAddress((void**)&ex,   g_ex);
    cudaGetSymbolAddress((void**)&h,    g_h);

    const int NH   = N_NODES * HEADS;
    const int gNH  = cdiv(NH, 256);
    const int gE   = cdiv(N_EDGES, 256);
    const int gEH  = cdiv(N_EDGES * HEADS, 256);
    const int gBig = cdiv(N_NODES, 8);

    // ======================= layer 1 (Fin=9, Fo=64) =======================
    gemm_big<9><<<gBig, 192>>>(feats, W1, feat);
    attn_dots<<<gNH, 256>>>(feat, al1, ar1, el, er, HF);
    init_ms<<<gNH, 256>>>(menc, s, NH);
    fill_zero<<<cdiv(N_NODES * HFO, 256), 256>>>(rst, N_NODES * HFO);
    edge_max<<<gE, 256>>>(src, dst, el, er, menc);
    edge_exp<<<gE, 256>>>(src, dst, el, er, menc, ex, s);
    edge_agg_big<<<gEH, 256>>>(src, dst, ex, s, feat, rst);
    head_sum<<<cdiv(N_NODES * HF, 256), 256>>>(rst, b1, h, HF, N_NODES * HF);

    // ======================= layer 2 (Fin=64, Fo=64) ======================
    gemm_big<64><<<gBig, 192>>>(h, W2, feat);
    attn_dots<<<gNH, 256>>>(feat, al2, ar2, el, er, HF);
    init_ms<<<gNH, 256>>>(menc, s, NH);
    fill_zero<<<cdiv(N_NODES * HFO, 256), 256>>>(rst, N_NODES * HFO);
    edge_max<<<gE, 256>>>(src, dst, el, er, menc);
    edge_exp<<<gE, 256>>>(src, dst, el, er, menc, ex, s);
    edge_agg_big<<<gEH, 256>>>(src, dst, ex, s, feat, rst);
    head_sum<<<cdiv(N_NODES * HF, 256), 256>>>(rst, b2, h, HF, N_NODES * HF);

    // ======================= layer 3 (Fin=64, Fo=2) =======================
    gemm_small<<<cdiv(N_NODES * HFO3, 256), 256>>>(h, W3, feat, HF, HFO3,
                                                   N_NODES * HFO3);
    attn_dots<<<gNH, 256>>>(feat, al3, ar3, el, er, NCLS);
    init_ms<<<gNH, 256>>>(menc, s, NH);
    fill_zero<<<cdiv(N_NODES * HFO3, 256), 256>>>(rst, N_NODES * HFO3);
    edge_max<<<gE, 256>>>(src, dst, el, er, menc);
    edge_exp<<<gE, 256>>>(src, dst, el, er, menc, ex, s);
    edge_agg_small<<<gE, 256>>>(src, dst, ex, s, feat, rst);
    head_sum<<<cdiv(N_NODES * NCLS, 256), 256>>>(rst, b3, out, NCLS,
                                                 N_NODES * NCLS);
}

// round 2
// speedup vs baseline: 2.6992x; 2.6992x over previous
#include <cuda_runtime.h>
#include <math_constants.h>

#define N_NODES 50000
#define N_EDGES 800000
#define HEADS   3
#define HF      64            // H_FEATS
#define HFO     (HEADS*HF)    // 192
#define NCLS    2
#define HFO3    (HEADS*NCLS)  // 6
#define NEG     0.2f
#define WPB     8             // warps per block for per-dst kernels

// ---------------- scratch (device globals; no allocation allowed) ----------
__device__ __align__(16) float g_feat [N_NODES * HFO];   // per-layer feat [N,H,Fo]
__device__ float g_el   [N_NODES * HEADS];
__device__ float g_er   [N_NODES * HEADS];
__device__ float g_h    [N_NODES * HF];                  // inter-layer node feats
__device__ float g_alpha[N_EDGES * HEADS];               // normalized attn (CSR order)
__device__ int   g_csrs [N_EDGES];                       // src node per CSR slot
__device__ int   g_rowp [N_NODES + 1];                   // CSR row pointers (by dst)
__device__ int   g_cnt  [N_NODES];                       // in-degree histogram
__device__ int   g_wpos [N_NODES];                       // scatter cursors

// ---------------- helpers ---------------------------------------------------
__device__ __forceinline__ float lrelu(float v) { return v > 0.f ? v : NEG * v; }
__device__ __forceinline__ float wred_max(float v) {
#pragma unroll
    for (int o = 16; o; o >>= 1) v = fmaxf(v, __shfl_xor_sync(~0u, v, o));
    return v;
}
__device__ __forceinline__ float wred_sum(float v) {
#pragma unroll
    for (int o = 16; o; o >>= 1) v += __shfl_xor_sync(~0u, v, o);
    return v;
}

// ================= CSR build ================================================
__global__ void zero_cnt() {
    int i = blockIdx.x * blockDim.x + threadIdx.x;
    if (i < N_NODES) g_cnt[i] = 0;
}
__global__ void hist_dst(const int* __restrict__ dst) {
    int e = blockIdx.x * blockDim.x + threadIdx.x;
    if (e < N_EDGES) atomicAdd(&g_cnt[dst[e]], 1);
}
// single-block exclusive scan over 50K counters (1024 threads, chunked)
__global__ void scan_rowptr() {
    __shared__ int wsum[32];
    __shared__ int s_carry;
    const int lane = threadIdx.x & 31, w = threadIdx.x >> 5;
    if (threadIdx.x == 0) s_carry = 0;
    __syncthreads();
    for (int base = 0; base < N_NODES; base += 1024) {
        int i = base + threadIdx.x;
        int v = (i < N_NODES) ? g_cnt[i] : 0;
        int x = v;
#pragma unroll
        for (int o = 1; o < 32; o <<= 1) {
            int y = __shfl_up_sync(~0u, x, o);
            if (lane >= o) x += y;
        }
        if (lane == 31) wsum[w] = x;
        __syncthreads();
        if (w == 0) {
            int y = wsum[lane];
#pragma unroll
            for (int o = 1; o < 32; o <<= 1) {
                int z = __shfl_up_sync(~0u, y, o);
                if (lane >= o) y += z;
            }
            wsum[lane] = y;
        }
        __syncthreads();
        int excl = x - v + (w > 0 ? wsum[w - 1] : 0) + s_carry;
        if (i < N_NODES) { g_rowp[i] = excl; g_wpos[i] = excl; }
        __syncthreads();
        if (threadIdx.x == 0) s_carry += wsum[31];
        __syncthreads();
    }
    if (threadIdx.x == 0) g_rowp[N_NODES] = s_carry;
}
__global__ void scatter_edges(const int* __restrict__ src, const int* __restrict__ dst) {
    int e = blockIdx.x * blockDim.x + threadIdx.x;
    if (e >= N_EDGES) return;
    int p = atomicAdd(&g_wpos[dst[e]], 1);
    g_csrs[p] = src[e];
}

// ================= GEMMs ====================================================
// feat = x @ W  (HFo = 192): 192 threads (one per column), 8 nodes/block
template <int FIN>
__global__ void gemm_big(const float* __restrict__ x,
                         const float* __restrict__ W,
                         float* __restrict__ feat) {
    __shared__ float xs[8 * FIN];
    const int t  = threadIdx.x;
    const int n0 = blockIdx.x * 8;
    for (int i = t; i < 8 * FIN; i += 192) {
        int node = n0 + i / FIN;
        xs[i] = (node < N_NODES) ? x[node * FIN + i % FIN] : 0.f;
    }
    __syncthreads();
    float acc[8];
#pragma unroll
    for (int i = 0; i < 8; i++) acc[i] = 0.f;
    for (int k = 0; k < FIN; k++) {
        float wv = __ldg(&W[k * HFO + t]);
#pragma unroll
        for (int i = 0; i < 8; i++) acc[i] += xs[i * FIN + k] * wv;
    }
#pragma unroll
    for (int i = 0; i < 8; i++) {
        int node = n0 + i;
        if (node < N_NODES) feat[node * HFO + t] = acc[i];
    }
}

__global__ void gemm_small(const float* __restrict__ x,
                           const float* __restrict__ W,
                           float* __restrict__ feat,
                           int Fin, int HFo, int total) {
    int idx = blockIdx.x * blockDim.x + threadIdx.x;
    if (idx >= total) return;
    int n = idx / HFo, c = idx % HFo;
    float acc = 0.f;
    const float* xr = x + n * Fin;
    for (int k = 0; k < Fin; k++) acc += xr[k] * __ldg(&W[k * HFo + c]);
    feat[idx] = acc;
}

// ================= attention dot products ===================================
__global__ void attn_dots(const float* __restrict__ feat,
                          const float* __restrict__ al,
                          const float* __restrict__ ar,
                          int Fo) {
    int idx = blockIdx.x * blockDim.x + threadIdx.x;   // n*HEADS + h
    if (idx >= N_NODES * HEADS) return;
    int n = idx / HEADS, h = idx % HEADS;
    const float* fp  = feat + (n * HEADS + h) * Fo;
    const float* alp = al + h * Fo;
    const float* arp = ar + h * Fo;
    float sl = 0.f, sr = 0.f;
    for (int f = 0; f < Fo; f++) {
        float v = fp[f];
        sl += v * __ldg(&alp[f]);
        sr += v * __ldg(&arp[f]);
    }
    g_el[idx] = sl;
    g_er[idx] = sr;
}

// ================= warp-per-dst edge softmax ================================
__global__ void softmax_csr() {
    const int lane = threadIdx.x & 31;
    const int d = blockIdx.x * WPB + (threadIdx.x >> 5);
    if (d >= N_NODES) return;
    const int beg = g_rowp[d], end = g_rowp[d + 1];
    if (beg == end) return;
    const float er0 = g_er[d * HEADS + 0];
    const float er1 = g_er[d * HEADS + 1];
    const float er2 = g_er[d * HEADS + 2];

    // pass 1: max
    float m0 = -CUDART_INF_F, m1 = m0, m2 = m0;
    for (int i = beg + lane; i < end; i += 32) {
        int s = __ldg(&g_csrs[i]);
        m0 = fmaxf(m0, lrelu(g_el[s * HEADS + 0] + er0));
        m1 = fmaxf(m1, lrelu(g_el[s * HEADS + 1] + er1));
        m2 = fmaxf(m2, lrelu(g_el[s * HEADS + 2] + er2));
    }
    m0 = wred_max(m0); m1 = wred_max(m1); m2 = wred_max(m2);

    // pass 2: exp + sum (store unnormalized exp)
    float s0 = 0.f, s1 = 0.f, s2 = 0.f;
    for (int i = beg + lane; i < end; i += 32) {
        int s = __ldg(&g_csrs[i]);
        float x0 = __expf(lrelu(g_el[s * HEADS + 0] + er0) - m0);
        float x1 = __expf(lrelu(g_el[s * HEADS + 1] + er1) - m1);
        float x2 = __expf(lrelu(g_el[s * HEADS + 2] + er2) - m2);
        g_alpha[i * HEADS + 0] = x0;
        g_alpha[i * HEADS + 1] = x1;
        g_alpha[i * HEADS + 2] = x2;
        s0 += x0; s1 += x1; s2 += x2;
    }
    s0 = wred_sum(s0); s1 = wred_sum(s1); s2 = wred_sum(s2);
    const float i0 = 1.f / s0, i1 = 1.f / s1, i2 = 1.f / s2;

    // pass 3: normalize
    for (int i = beg + lane; i < end; i += 32) {
        g_alpha[i * HEADS + 0] *= i0;
        g_alpha[i * HEADS + 1] *= i1;
        g_alpha[i * HEADS + 2] *= i2;
    }
}

// ================= warp-per-dst aggregation, Fo = 64 ========================
// 192 register accumulators per warp (6/lane); fused head-sum + bias epilogue
__global__ void agg_csr_big(const float* __restrict__ feat,
                            const float* __restrict__ bias,
                            float* __restrict__ out) {
    const int lane = threadIdx.x & 31;
    const int d = blockIdx.x * WPB + (threadIdx.x >> 5);
    if (d >= N_NODES) return;
    const int beg = g_rowp[d], end = g_rowp[d + 1];

    float a0c = 0.f, a1c = 0.f, a2c = 0.f, a3c = 0.f, a4c = 0.f, a5c = 0.f;
#pragma unroll 2
    for (int i = beg; i < end; ++i) {
        const int s = __ldg(&g_csrs[i]);                 // warp-broadcast
        const float w0 = __ldg(&g_alpha[i * HEADS + 0]);
        const float w1 = __ldg(&g_alpha[i * HEADS + 1]);
        const float w2 = __ldg(&g_alpha[i * HEADS + 2]);
        const float* fp = feat + (long)s * HFO;
        a0c += w0 * __ldg(fp + lane);
        a1c += w0 * __ldg(fp + lane + 32);
        a2c += w1 * __ldg(fp + lane + 64);
        a3c += w1 * __ldg(fp + lane + 96);
        a4c += w2 * __ldg(fp + lane + 128);
        a5c += w2 * __ldg(fp + lane + 160);
    }
    // h[d][c] = sum_h (agg[h][c] + b[h*64+c])
    float bs0 = __ldg(&bias[lane])      + __ldg(&bias[64 + lane])  + __ldg(&bias[128 + lane]);
    float bs1 = __ldg(&bias[32 + lane]) + __ldg(&bias[96 + lane])  + __ldg(&bias[160 + lane]);
    out[d * HF + lane]      = a0c + a2c + a4c + bs0;
    out[d * HF + 32 + lane] = a1c + a3c + a5c + bs1;
}

// ================= warp-per-dst aggregation, Fo = 2 (layer 3) ===============
__global__ void agg_csr_small(const float* __restrict__ feat,
                              const float* __restrict__ bias,
                              float* __restrict__ out) {
    const int lane = threadIdx.x & 31;
    const int d = blockIdx.x * WPB + (threadIdx.x >> 5);
    if (d >= N_NODES) return;
    const int beg = g_rowp[d], end = g_rowp[d + 1];
    float c0 = 0.f, c1 = 0.f;   // head-summed class accumulators
    for (int i = beg + lane; i < end; i += 32) {
        int s = __ldg(&g_csrs[i]);
        const float* fp = feat + s * HFO3;
#pragma unroll
        for (int h = 0; h < HEADS; h++) {
            float a = __ldg(&g_alpha[i * HEADS + h]);
            c0 += a * __ldg(fp + h * NCLS + 0);
            c1 += a * __ldg(fp + h * NCLS + 1);
        }
    }
    c0 = wred_sum(c0); c1 = wred_sum(c1);
    if (lane == 0) {
        float b0 = __ldg(&bias[0]) + __ldg(&bias[2]) + __ldg(&bias[4]);
        float b1 = __ldg(&bias[1]) + __ldg(&bias[3]) + __ldg(&bias[5]);
        out[d * NCLS + 0] = c0 + b0;
        out[d * NCLS + 1] = c1 + b1;
    }
}

// ================= host driver ==============================================
static inline int cdiv(int a, int b) { return (a + b - 1) / b; }

extern "C" void kernel_launch(void* const* d_in, const int* in_sizes, int n_in,
                              void* d_out, int out_size) {
    const float* feats = (const float*)d_in[0];
    const int*   src   = (const int*)  d_in[1];
    const int*   dst   = (const int*)  d_in[2];
    const float* W1 = (const float*)d_in[3],  *al1 = (const float*)d_in[4];
    const float* ar1= (const float*)d_in[5],  *b1  = (const float*)d_in[6];
    const float* W2 = (const float*)d_in[7],  *al2 = (const float*)d_in[8];
    const float* ar2= (const float*)d_in[9],  *b2  = (const float*)d_in[10];
    const float* W3 = (const float*)d_in[11], *al3 = (const float*)d_in[12];
    const float* ar3= (const float*)d_in[13], *b3  = (const float*)d_in[14];
    float* out = (float*)d_out;

    float *feat, *h;
    cudaGetSymbolAddress((void**)&feat, g_feat);
    cudaGetSymbolAddress((void**)&h,    g_h);

    const int gNH  = cdiv(N_NODES * HEADS, 256);
    const int gE   = cdiv(N_EDGES, 256);
    const int gBig = cdiv(N_NODES, 8);
    const int gDst = cdiv(N_NODES, WPB);

    // -------- CSR build (graph shared by all 3 layers) --------
    zero_cnt<<<cdiv(N_NODES, 256), 256>>>();
    hist_dst<<<gE, 256>>>(dst);
    scan_rowptr<<<1, 1024>>>();
    scatter_edges<<<gE, 256>>>(src, dst);

    // -------- layer 1 (Fin=9, Fo=64) --------
    gemm_big<9><<<gBig, 192>>>(feats, W1, feat);
    attn_dots<<<gNH, 256>>>(feat, al1, ar1, HF);
    softmax_csr<<<gDst, 32 * WPB>>>();
    agg_csr_big<<<gDst, 32 * WPB>>>(feat, b1, h);

    // -------- layer 2 (Fin=64, Fo=64) --------
    gemm_big<64><<<gBig, 192>>>(h, W2, feat);
    attn_dots<<<gNH, 256>>>(feat, al2, ar2, HF);
    softmax_csr<<<gDst, 32 * WPB>>>();
    agg_csr_big<<<gDst, 32 * WPB>>>(feat, b2, h);

    // -------- layer 3 (Fin=64, Fo=2) --------
    gemm_small<<<cdiv(N_NODES * HFO3, 256), 256>>>(h, W3, feat, HF, HFO3,
                                                   N_NODES * HFO3);
    attn_dots<<<gNH, 256>>>(feat, al3, ar3, NCLS);
    softmax_csr<<<gDst, 32 * WPB>>>();
    agg_csr_small<<<gDst, 32 * WPB>>>(feat, b3, out);
}

// round 3
// speedup vs baseline: 2.8313x; 1.0489x over previous
#include <cuda_runtime.h>
#include <math_constants.h>

#define N_NODES 50000
#define N_EDGES 800000
#define HEADS   3
#define HF      64            // H_FEATS
#define HFO     (HEADS*HF)    // 192
#define NCLS    2
#define HFO3    (HEADS*NCLS)  // 6
#define NEG     0.2f
#define WPB     8             // warps per block for per-dst kernels

// ---------------- scratch (device globals; no allocation allowed) ----------
__device__ __align__(16) float g_feat[N_NODES * HFO];   // per-layer feat [N,H,Fo]
__device__ __align__(16) float g_el  [N_NODES * 4];     // el per node, padded float4
__device__ __align__(16) float g_er  [N_NODES * 4];     // er per node, padded float4
__device__ float g_h   [N_NODES * HF];                  // inter-layer node feats
__device__ int   g_csrs[N_EDGES];                       // src node per CSR slot
__device__ int   g_rowp[N_NODES + 1];                   // CSR row pointers (by dst)
__device__ int   g_cnt [N_NODES];                       // in-degree histogram
__device__ int   g_wpos[N_NODES];                       // scatter cursors

// ---------------- helpers ---------------------------------------------------
__device__ __forceinline__ float lrelu(float v) { return v > 0.f ? v : NEG * v; }
__device__ __forceinline__ float wred_sum(float v) {
#pragma unroll
    for (int o = 16; o; o >>= 1) v += __shfl_xor_sync(~0u, v, o);
    return v;
}

// ================= CSR build ================================================
__global__ void zero_cnt() {
    int i = blockIdx.x * blockDim.x + threadIdx.x;
    if (i < N_NODES) g_cnt[i] = 0;
}
__global__ void hist_dst(const int* __restrict__ dst) {
    int e = blockIdx.x * blockDim.x + threadIdx.x;
    if (e < N_EDGES) atomicAdd(&g_cnt[__ldg(&dst[e])], 1);
}
// single-block exclusive scan over 50K counters (1024 threads, chunked)
__global__ void scan_rowptr() {
    __shared__ int wsum[32];
    __shared__ int s_carry;
    const int lane = threadIdx.x & 31, w = threadIdx.x >> 5;
    if (threadIdx.x == 0) s_carry = 0;
    __syncthreads();
    for (int base = 0; base < N_NODES; base += 1024) {
        int i = base + threadIdx.x;
        int v = (i < N_NODES) ? g_cnt[i] : 0;
        int x = v;
#pragma unroll
        for (int o = 1; o < 32; o <<= 1) {
            int y = __shfl_up_sync(~0u, x, o);
            if (lane >= o) x += y;
        }
        if (lane == 31) wsum[w] = x;
        __syncthreads();
        if (w == 0) {
            int y = wsum[lane];
#pragma unroll
            for (int o = 1; o < 32; o <<= 1) {
                int z = __shfl_up_sync(~0u, y, o);
                if (lane >= o) y += z;
            }
            wsum[lane] = y;
        }
        __syncthreads();
        int excl = x - v + (w > 0 ? wsum[w - 1] : 0) + s_carry;
        if (i < N_NODES) { g_rowp[i] = excl; g_wpos[i] = excl; }
        __syncthreads();
        if (threadIdx.x == 0) s_carry += wsum[31];
        __syncthreads();
    }
    if (threadIdx.x == 0) g_rowp[N_NODES] = s_carry;
}
__global__ void scatter_edges(const int* __restrict__ src, const int* __restrict__ dst) {
    int e = blockIdx.x * blockDim.x + threadIdx.x;
    if (e >= N_EDGES) return;
    int p = atomicAdd(&g_wpos[__ldg(&dst[e])], 1);
    g_csrs[p] = __ldg(&src[e]);
}

// ================= GEMM: feat = x @ W (HFo = 192), register-tiled ===========
// block: 192 threads = 4 node-groups x 48 col-groups; thread: 8 nodes x 4 cols
template <int FIN>
__global__ void gemm_reg(const float* __restrict__ x,
                         const float* __restrict__ W,
                         float* __restrict__ feat) {
    __shared__ float xs[32 * FIN];
    const int tid = threadIdx.x;
    const int cg  = tid % 48;          // cols 4*cg .. 4*cg+3
    const int ng  = tid / 48;          // nodes ng*8 .. ng*8+7 (within tile)
    const int n0  = blockIdx.x * 32;

    for (int i = tid; i < 32 * FIN; i += 192) {
        int node = n0 + i / FIN;
        xs[i] = (node < N_NODES) ? x[node * FIN + i % FIN] : 0.f;
    }
    __syncthreads();

    float acc[8][4];
#pragma unroll
    for (int i = 0; i < 8; i++)
#pragma unroll
        for (int j = 0; j < 4; j++) acc[i][j] = 0.f;

    const float* xb = xs + ng * 8 * FIN;
    for (int k = 0; k < FIN; k++) {
        float4 w = __ldg(reinterpret_cast<const float4*>(W + k * HFO + cg * 4));
#pragma unroll
        for (int i = 0; i < 8; i++) {
            float xv = xb[i * FIN + k];
            acc[i][0] += xv * w.x;
            acc[i][1] += xv * w.y;
            acc[i][2] += xv * w.z;
            acc[i][3] += xv * w.w;
        }
    }
#pragma unroll
    for (int i = 0; i < 8; i++) {
        int node = n0 + ng * 8 + i;
        if (node < N_NODES) {
            float4 v = make_float4(acc[i][0], acc[i][1], acc[i][2], acc[i][3]);
            *reinterpret_cast<float4*>(feat + node * HFO + cg * 4) = v;
        }
    }
}

// ================= GEMM: small output (layer 3, HFo = 6) ====================
__global__ void gemm_small(const float* __restrict__ x,
                           const float* __restrict__ W,
                           float* __restrict__ feat) {
    int idx = blockIdx.x * blockDim.x + threadIdx.x;
    if (idx >= N_NODES * HFO3) return;
    int n = idx / HFO3, c = idx % HFO3;
    float acc = 0.f;
    const float* xr = x + n * HF;
    for (int k = 0; k < HF; k++) acc += xr[k] * __ldg(&W[k * HFO3 + c]);
    feat[idx] = acc;
}

// ================= attention dot products -> padded float4 el/er ============
__global__ void attn_dots(const float* __restrict__ feat,
                          const float* __restrict__ al,
                          const float* __restrict__ ar,
                          int Fo) {
    int idx = blockIdx.x * blockDim.x + threadIdx.x;   // n*HEADS + h
    if (idx >= N_NODES * HEADS) return;
    int n = idx / HEADS, h = idx % HEADS;
    const float* fp  = feat + (n * HEADS + h) * Fo;
    const float* alp = al + h * Fo;
    const float* arp = ar + h * Fo;
    float sl = 0.f, sr = 0.f;
    for (int f = 0; f < Fo; f++) {
        float v = fp[f];
        sl += v * __ldg(&alp[f]);
        sr += v * __ldg(&arp[f]);
    }
    g_el[n * 4 + h] = sl;
    g_er[n * 4 + h] = sr;
}

// ================= fused softmax + aggregation, Fo = 64 =====================
// one warp per dst; single pass over edges; normalization factored out.
__global__ void agg_big(const float* __restrict__ feat,
                        const float* __restrict__ bias,
                        float* __restrict__ out) {
    const int lane = threadIdx.x & 31;
    const int d = blockIdx.x * WPB + (threadIdx.x >> 5);
    if (d >= N_NODES) return;
    const int beg = g_rowp[d], end = g_rowp[d + 1];

    const float4 er = *reinterpret_cast<const float4*>(g_er + 4 * d);
    float s0 = 0.f, s1 = 0.f, s2 = 0.f;                  // unnormalized sums
    float a0 = 0.f, a1 = 0.f, a2 = 0.f, a3 = 0.f, a4 = 0.f, a5 = 0.f;

    for (int base = beg; base < end; base += 32) {
        int i = base + lane;
        int   sl  = 0;
        float w0l = 0.f, w1l = 0.f, w2l = 0.f;
        if (i < end) {
            sl = __ldg(&g_csrs[i]);
            float4 e = *reinterpret_cast<const float4*>(g_el + 4 * sl);
            w0l = __expf(lrelu(e.x + er.x));
            w1l = __expf(lrelu(e.y + er.y));
            w2l = __expf(lrelu(e.z + er.z));
        }
        s0 += w0l; s1 += w1l; s2 += w2l;
        const int cnt = min(32, end - base);
        for (int j = 0; j < cnt; j++) {
            const int   s  = __shfl_sync(~0u, sl,  j);
            const float w0 = __shfl_sync(~0u, w0l, j);
            const float w1 = __shfl_sync(~0u, w1l, j);
            const float w2 = __shfl_sync(~0u, w2l, j);
            const float* fp = feat + s * HFO;
            a0 += w0 * __ldg(fp + lane);
            a1 += w0 * __ldg(fp + lane + 32);
            a2 += w1 * __ldg(fp + lane + 64);
            a3 += w1 * __ldg(fp + lane + 96);
            a4 += w2 * __ldg(fp + lane + 128);
            a5 += w2 * __ldg(fp + lane + 160);
        }
    }
    s0 = wred_sum(s0); s1 = wred_sum(s1); s2 = wred_sum(s2);
    const float i0 = s0 > 0.f ? 1.f / s0 : 0.f;
    const float i1 = s1 > 0.f ? 1.f / s1 : 0.f;
    const float i2 = s2 > 0.f ? 1.f / s2 : 0.f;

    float bs0 = __ldg(&bias[lane])      + __ldg(&bias[64 + lane]) + __ldg(&bias[128 + lane]);
    float bs1 = __ldg(&bias[32 + lane]) + __ldg(&bias[96 + lane]) + __ldg(&bias[160 + lane]);
    out[d * HF + lane]      = a0 * i0 + a2 * i1 + a4 * i2 + bs0;
    out[d * HF + 32 + lane] = a1 * i0 + a3 * i1 + a5 * i2 + bs1;
}

// ================= fused softmax + aggregation, Fo = 2 (layer 3) ============
__global__ void agg_small(const float* __restrict__ feat,
                          const float* __restrict__ bias,
                          float* __restrict__ out) {
    const int lane = threadIdx.x & 31;
    const int d = blockIdx.x * WPB + (threadIdx.x >> 5);
    if (d >= N_NODES) return;
    const int beg = g_rowp[d], end = g_rowp[d + 1];
    const float4 er = *reinterpret_cast<const float4*>(g_er + 4 * d);

    float s0 = 0.f, s1 = 0.f, s2 = 0.f;
    float c00 = 0.f, c01 = 0.f, c10 = 0.f, c11 = 0.f, c20 = 0.f, c21 = 0.f;
    for (int i = beg + lane; i < end; i += 32) {
        int s = __ldg(&g_csrs[i]);
        float4 e = *reinterpret_cast<const float4*>(g_el + 4 * s);
        float w0 = __expf(lrelu(e.x + er.x));
        float w1 = __expf(lrelu(e.y + er.y));
        float w2 = __expf(lrelu(e.z + er.z));
        s0 += w0; s1 += w1; s2 += w2;
        const float* fp = feat + s * HFO3;
        c00 += w0 * __ldg(fp + 0); c01 += w0 * __ldg(fp + 1);
        c10 += w1 * __ldg(fp + 2); c11 += w1 * __ldg(fp + 3);
        c20 += w2 * __ldg(fp + 4); c21 += w2 * __ldg(fp + 5);
    }
    s0 = wred_sum(s0); s1 = wred_sum(s1); s2 = wred_sum(s2);
    c00 = wred_sum(c00); c01 = wred_sum(c01);
    c10 = wred_sum(c10); c11 = wred_sum(c11);
    c20 = wred_sum(c20); c21 = wred_sum(c21);
    if (lane == 0) {
        const float i0 = s0 > 0.f ? 1.f / s0 : 0.f;
        const float i1 = s1 > 0.f ? 1.f / s1 : 0.f;
        const float i2 = s2 > 0.f ? 1.f / s2 : 0.f;
        float b0 = __ldg(&bias[0]) + __ldg(&bias[2]) + __ldg(&bias[4]);
        float b1 = __ldg(&bias[1]) + __ldg(&bias[3]) + __ldg(&bias[5]);
        out[d * NCLS + 0] = c00 * i0 + c10 * i1 + c20 * i2 + b0;
        out[d * NCLS + 1] = c01 * i0 + c11 * i1 + c21 * i2 + b1;
    }
}

// ================= host driver ==============================================
static inline int cdiv(int a, int b) { return (a + b - 1) / b; }

extern "C" void kernel_launch(void* const* d_in, const int* in_sizes, int n_in,
                              void* d_out, int out_size) {
    const float* feats = (const float*)d_in[0];
    const int*   src   = (const int*)  d_in[1];
    const int*   dst   = (const int*)  d_in[2];
    const float* W1 = (const float*)d_in[3],  *al1 = (const float*)d_in[4];
    const float* ar1= (const float*)d_in[5],  *b1  = (const float*)d_in[6];
    const float* W2 = (const float*)d_in[7],  *al2 = (const float*)d_in[8];
    const float* ar2= (const float*)d_in[9],  *b2  = (const float*)d_in[10];
    const float* W3 = (const float*)d_in[11], *al3 = (const float*)d_in[12];
    const float* ar3= (const float*)d_in[13], *b3  = (const float*)d_in[14];
    float* out = (float*)d_out;

    float *feat, *h;
    cudaGetSymbolAddress((void**)&feat, g_feat);
    cudaGetSymbolAddress((void**)&h,    g_h);

    const int gNH   = cdiv(N_NODES * HEADS, 256);
    const int gE    = cdiv(N_EDGES, 256);
    const int gTile = cdiv(N_NODES, 32);
    const int gDst  = cdiv(N_NODES, WPB);

    // -------- CSR build (graph shared by all 3 layers) --------
    zero_cnt<<<cdiv(N_NODES, 256), 256>>>();
    hist_dst<<<gE, 256>>>(dst);
    scan_rowptr<<<1, 1024>>>();
    scatter_edges<<<gE, 256>>>(src, dst);

    // -------- layer 1 (Fin=9, Fo=64) --------
    gemm_reg<9><<<gTile, 192>>>(feats, W1, feat);
    attn_dots<<<gNH, 256>>>(feat, al1, ar1, HF);
    agg_big<<<gDst, 32 * WPB>>>(feat, b1, h);

    // -------- layer 2 (Fin=64, Fo=64) --------
    gemm_reg<64><<<gTile, 192>>>(h, W2, feat);
    attn_dots<<<gNH, 256>>>(feat, al2, ar2, HF);
    agg_big<<<gDst, 32 * WPB>>>(feat, b2, h);

    // -------- layer 3 (Fin=64, Fo=2) --------
    gemm_small<<<cdiv(N_NODES * HFO3, 256), 256>>>(h, W3, feat);
    attn_dots<<<gNH, 256>>>(feat, al3, ar3, NCLS);
    agg_small<<<gDst, 32 * WPB>>>(feat, b3, out);
}

// round 4
// speedup vs baseline: 4.1904x; 1.4800x over previous
#include <cuda_runtime.h>
#include <cuda_fp16.h>
#include <math_constants.h>

#define N_NODES 50000
#define N_EDGES 800000
#define HEADS   3
#define HF      64            // H_FEATS
#define HFO     (HEADS*HF)    // 192
#define NH2     (HFO/2)       // 96 half2 per node row
#define NCLS    2
#define HFO3    (HEADS*NCLS)  // 6
#define NEG     0.2f
#define WPB     8             // warps per block for per-dst kernels
#define EPT     4             // edges per thread in CSR-build kernels

// ---------------- scratch (device globals; no allocation allowed) ----------
__device__ __align__(16) __half2 g_feath[N_NODES * NH2];  // fp16 feat [N][96] half2
__device__ __align__(16) float   g_el  [N_NODES * 4];     // el per node (padded float4)
__device__ __align__(16) float   g_er  [N_NODES * 4];     // er per node (padded float4)
__device__ float g_h    [N_NODES * HF];                   // inter-layer node feats (fp32)
__device__ float g_feat3[N_NODES * HFO3];                 // layer-3 feat (fp32)
__device__ int   g_csrs [N_EDGES];                        // src node per CSR slot
__device__ int   g_rowp [N_NODES + 1];                    // CSR row pointers (by dst)
__device__ int   g_cnt  [N_NODES];                        // in-degree histogram
__device__ int   g_wpos [N_NODES];                        // scatter cursors

// ---------------- helpers ---------------------------------------------------
__device__ __forceinline__ float lrelu(float v) { return v > 0.f ? v : NEG * v; }
__device__ __forceinline__ float wred_sum(float v) {
#pragma unroll
    for (int o = 16; o; o >>= 1) v += __shfl_xor_sync(~0u, v, o);
    return v;
}

// ================= CSR build ================================================
__global__ void hist_dst(const int* __restrict__ dst) {
    int e0 = (blockIdx.x * blockDim.x + threadIdx.x) * EPT;
#pragma unroll
    for (int k = 0; k < EPT; k++) {
        int e = e0 + k;
        if (e < N_EDGES) atomicAdd(&g_cnt[__ldg(&dst[e])], 1);
    }
}
// single-block exclusive scan over 50K counters (1024 threads, chunked)
__global__ void scan_rowptr() {
    __shared__ int wsum[32];
    __shared__ int s_carry;
    const int lane = threadIdx.x & 31, w = threadIdx.x >> 5;
    if (threadIdx.x == 0) s_carry = 0;
    __syncthreads();
    for (int base = 0; base < N_NODES; base += 1024) {
        int i = base + threadIdx.x;
        int v = (i < N_NODES) ? g_cnt[i] : 0;
        int x = v;
#pragma unroll
        for (int o = 1; o < 32; o <<= 1) {
            int y = __shfl_up_sync(~0u, x, o);
            if (lane >= o) x += y;
        }
        if (lane == 31) wsum[w] = x;
        __syncthreads();
        if (w == 0) {
            int y = wsum[lane];
#pragma unroll
            for (int o = 1; o < 32; o <<= 1) {
                int z = __shfl_up_sync(~0u, y, o);
                if (lane >= o) y += z;
            }
            wsum[lane] = y;
        }
        __syncthreads();
        int excl = x - v + (w > 0 ? wsum[w - 1] : 0) + s_carry;
        if (i < N_NODES) { g_rowp[i] = excl; g_wpos[i] = excl; }
        __syncthreads();
        if (threadIdx.x == 0) s_carry += wsum[31];
        __syncthreads();
    }
    if (threadIdx.x == 0) g_rowp[N_NODES] = s_carry;
}
__global__ void scatter_edges(const int* __restrict__ src, const int* __restrict__ dst) {
    int e0 = (blockIdx.x * blockDim.x + threadIdx.x) * EPT;
#pragma unroll
    for (int k = 0; k < EPT; k++) {
        int e = e0 + k;
        if (e < N_EDGES) {
            int p = atomicAdd(&g_wpos[__ldg(&dst[e])], 1);
            g_csrs[p] = __ldg(&src[e]);
        }
    }
}

// ================= fused GEMM + attn dots (HFo = 192) =======================
// block: 192 threads = 4 node-groups x 48 col-groups; thread: 8 nodes x 4 cols.
// fp32 compute; epilogue: el/er from fp32 accumulators (width-16 shfl reduce),
// feat stored as half2.
template <int FIN>
__global__ void gemm_attn(const float* __restrict__ x,
                          const float* __restrict__ W,
                          const float* __restrict__ al,
                          const float* __restrict__ ar,
                          __half2* __restrict__ feath) {
    __shared__ float xs[32 * FIN];
    const int tid = threadIdx.x;
    const int cg  = tid % 48;          // cols 4*cg .. 4*cg+3
    const int ng  = tid / 48;          // node sub-tile (8 nodes)
    const int n0  = blockIdx.x * 32;
    const int head = cg / 16;          // 16 col-groups per head
    const int c64  = (cg % 16) * 4;    // col offset within head

    for (int i = tid; i < 32 * FIN; i += 192) {
        int node = n0 + i / FIN;
        xs[i] = (node < N_NODES) ? x[node * FIN + i % FIN] : 0.f;
    }
    __syncthreads();

    float acc[8][4];
#pragma unroll
    for (int i = 0; i < 8; i++)
#pragma unroll
        for (int j = 0; j < 4; j++) acc[i][j] = 0.f;

    const float* xb = xs + ng * 8 * FIN;
    for (int k = 0; k < FIN; k++) {
        float4 w = __ldg(reinterpret_cast<const float4*>(W + k * HFO + cg * 4));
#pragma unroll
        for (int i = 0; i < 8; i++) {
            float xv = xb[i * FIN + k];
            acc[i][0] += xv * w.x;
            acc[i][1] += xv * w.y;
            acc[i][2] += xv * w.z;
            acc[i][3] += xv * w.w;
        }
    }

    // ---- store feat as half2, cols 4cg..4cg+3 -> half2 slots 2cg, 2cg+1 ----
#pragma unroll
    for (int i = 0; i < 8; i++) {
        int node = n0 + ng * 8 + i;
        if (node < N_NODES) {
            feath[node * NH2 + cg * 2]     = __floats2half2_rn(acc[i][0], acc[i][1]);
            feath[node * NH2 + cg * 2 + 1] = __floats2half2_rn(acc[i][2], acc[i][3]);
        }
    }

    // ---- fused attn dots: reduce over the 16 col-groups of this head -------
    float a0 = __ldg(&al[head * HF + c64 + 0]), a1 = __ldg(&al[head * HF + c64 + 1]);
    float a2 = __ldg(&al[head * HF + c64 + 2]), a3 = __ldg(&al[head * HF + c64 + 3]);
    float r0 = __ldg(&ar[head * HF + c64 + 0]), r1 = __ldg(&ar[head * HF + c64 + 1]);
    float r2 = __ldg(&ar[head * HF + c64 + 2]), r3 = __ldg(&ar[head * HF + c64 + 3]);
#pragma unroll
    for (int i = 0; i < 8; i++) {
        float sl = acc[i][0]*a0 + acc[i][1]*a1 + acc[i][2]*a2 + acc[i][3]*a3;
        float sr = acc[i][0]*r0 + acc[i][1]*r1 + acc[i][2]*r2 + acc[i][3]*r3;
        // groups of 16 consecutive threads are always within one warp
#pragma unroll
        for (int o = 8; o; o >>= 1) {
            sl += __shfl_down_sync(~0u, sl, o, 16);
            sr += __shfl_down_sync(~0u, sr, o, 16);
        }
        if ((tid & 15) == 0) {
            int node = n0 + ng * 8 + i;
            if (node < N_NODES) {
                g_el[node * 4 + head] = sl;
                g_er[node * 4 + head] = sr;
            }
        }
    }
}

// ================= fused layer-3 GEMM + attn dots (HFo = 6) =================
__global__ void gemm3_attn(const float* __restrict__ x,
                           const float* __restrict__ W,
                           const float* __restrict__ al,
                           const float* __restrict__ ar) {
    int n = blockIdx.x * blockDim.x + threadIdx.x;
    if (n >= N_NODES) return;
    float acc[HFO3];
#pragma unroll
    for (int c = 0; c < HFO3; c++) acc[c] = 0.f;
    const float4* xr = reinterpret_cast<const float4*>(x + n * HF);
    for (int k4 = 0; k4 < HF / 4; k4++) {
        float4 xv = __ldg(xr + k4);
#pragma unroll
        for (int c = 0; c < HFO3; c++) {
            acc[c] += xv.x * __ldg(&W[(k4*4+0) * HFO3 + c]);
            acc[c] += xv.y * __ldg(&W[(k4*4+1) * HFO3 + c]);
            acc[c] += xv.z * __ldg(&W[(k4*4+2) * HFO3 + c]);
            acc[c] += xv.w * __ldg(&W[(k4*4+3) * HFO3 + c]);
        }
    }
#pragma unroll
    for (int c = 0; c < HFO3; c++) g_feat3[n * HFO3 + c] = acc[c];
#pragma unroll
    for (int h = 0; h < HEADS; h++) {
        g_el[n * 4 + h] = acc[h*NCLS+0] * __ldg(&al[h*NCLS+0]) + acc[h*NCLS+1] * __ldg(&al[h*NCLS+1]);
        g_er[n * 4 + h] = acc[h*NCLS+0] * __ldg(&ar[h*NCLS+0]) + acc[h*NCLS+1] * __ldg(&ar[h*NCLS+1]);
    }
}

// ================= fused softmax + aggregation, Fo = 64, fp16 gather ========
// one warp per dst; single pass; normalization factored out of the sum.
__global__ void agg_big(const __half2* __restrict__ feath,
                        const float* __restrict__ bias,
                        float* __restrict__ out) {
    const int lane = threadIdx.x & 31;
    const int d = blockIdx.x * WPB + (threadIdx.x >> 5);
    if (d >= N_NODES) return;
    const int beg = g_rowp[d], end = g_rowp[d + 1];

    const float4 er = *reinterpret_cast<const float4*>(g_er + 4 * d);
    float s0 = 0.f, s1 = 0.f, s2 = 0.f;                  // unnormalized weight sums
    float a0 = 0.f, a1 = 0.f, a2 = 0.f, a3 = 0.f, a4 = 0.f, a5 = 0.f;

    for (int base = beg; base < end; base += 32) {
        int i = base + lane;
        int   sl  = 0;
        float w0l = 0.f, w1l = 0.f, w2l = 0.f;
        if (i < end) {
            sl = __ldg(&g_csrs[i]);
            float4 e = *reinterpret_cast<const float4*>(g_el + 4 * sl);
            w0l = __expf(lrelu(e.x + er.x));
            w1l = __expf(lrelu(e.y + er.y));
            w2l = __expf(lrelu(e.z + er.z));
        }
        s0 += w0l; s1 += w1l; s2 += w2l;
        const int cnt = min(32, end - base);
        for (int j = 0; j < cnt; j++) {
            const int   s  = __shfl_sync(~0u, sl,  j);
            const float w0 = __shfl_sync(~0u, w0l, j);
            const float w1 = __shfl_sync(~0u, w1l, j);
            const float w2 = __shfl_sync(~0u, w2l, j);
            const __half2* fp = feath + s * NH2;
            float2 f0 = __half22float2(__ldg(fp + lane));        // head0 cols 2l,2l+1
            float2 f1 = __half22float2(__ldg(fp + lane + 32));   // head1
            float2 f2 = __half22float2(__ldg(fp + lane + 64));   // head2
            a0 += w0 * f0.x;  a1 += w0 * f0.y;
            a2 += w1 * f1.x;  a3 += w1 * f1.y;
            a4 += w2 * f2.x;  a5 += w2 * f2.y;
        }
    }
    s0 = wred_sum(s0); s1 = wred_sum(s1); s2 = wred_sum(s2);
    const float i0 = s0 > 0.f ? 1.f / s0 : 0.f;
    const float i1 = s1 > 0.f ? 1.f / s1 : 0.f;
    const float i2 = s2 > 0.f ? 1.f / s2 : 0.f;

    // head-sum + bias; lane owns output cols 2*lane, 2*lane+1
    const int c0 = 2 * lane, c1 = 2 * lane + 1;
    float b0 = __ldg(&bias[c0]) + __ldg(&bias[HF + c0]) + __ldg(&bias[2*HF + c0]);
    float b1 = __ldg(&bias[c1]) + __ldg(&bias[HF + c1]) + __ldg(&bias[2*HF + c1]);
    float2 o;
    o.x = a0 * i0 + a2 * i1 + a4 * i2 + b0;
    o.y = a1 * i0 + a3 * i1 + a5 * i2 + b1;
    *reinterpret_cast<float2*>(out + d * HF + c0) = o;
}

// ================= fused softmax + aggregation, Fo = 2 (layer 3) ============
__global__ void agg_small(const float* __restrict__ feat,
                          const float* __restrict__ bias,
                          float* __restrict__ out) {
    const int lane = threadIdx.x & 31;
    const int d = blockIdx.x * WPB + (threadIdx.x >> 5);
    if (d >= N_NODES) return;
    const int beg = g_rowp[d], end = g_rowp[d + 1];
    const float4 er = *reinterpret_cast<const float4*>(g_er + 4 * d);

    float s0 = 0.f, s1 = 0.f, s2 = 0.f;
    float c00 = 0.f, c01 = 0.f, c10 = 0.f, c11 = 0.f, c20 = 0.f, c21 = 0.f;
    for (int i = beg + lane; i < end; i += 32) {
        int s = __ldg(&g_csrs[i]);
        float4 e = *reinterpret_cast<const float4*>(g_el + 4 * s);
        float w0 = __expf(lrelu(e.x + er.x));
        float w1 = __expf(lrelu(e.y + er.y));
        float w2 = __expf(lrelu(e.z + er.z));
        s0 += w0; s1 += w1; s2 += w2;
        const float* fp = feat + s * HFO3;
        c00 += w0 * __ldg(fp + 0); c01 += w0 * __ldg(fp + 1);
        c10 += w1 * __ldg(fp + 2); c11 += w1 * __ldg(fp + 3);
        c20 += w2 * __ldg(fp + 4); c21 += w2 * __ldg(fp + 5);
    }
    s0 = wred_sum(s0); s1 = wred_sum(s1); s2 = wred_sum(s2);
    c00 = wred_sum(c00); c01 = wred_sum(c01);
    c10 = wred_sum(c10); c11 = wred_sum(c11);
    c20 = wred_sum(c20); c21 = wred_sum(c21);
    if (lane == 0) {
        const float i0 = s0 > 0.f ? 1.f / s0 : 0.f;
        const float i1 = s1 > 0.f ? 1.f / s1 : 0.f;
        const float i2 = s2 > 0.f ? 1.f / s2 : 0.f;
        float b0 = __ldg(&bias[0]) + __ldg(&bias[2]) + __ldg(&bias[4]);
        float b1 = __ldg(&bias[1]) + __ldg(&bias[3]) + __ldg(&bias[5]);
        out[d * NCLS + 0] = c00 * i0 + c10 * i1 + c20 * i2 + b0;
        out[d * NCLS + 1] = c01 * i0 + c11 * i1 + c21 * i2 + b1;
    }
}

// ================= host driver ==============================================
static inline int cdiv(int a, int b) { return (a + b - 1) / b; }

extern "C" void kernel_launch(void* const* d_in, const int* in_sizes, int n_in,
                              void* d_out, int out_size) {
    const float* feats = (const float*)d_in[0];
    const int*   src   = (const int*)  d_in[1];
    const int*   dst   = (const int*)  d_in[2];
    const float* W1 = (const float*)d_in[3],  *al1 = (const float*)d_in[4];
    const float* ar1= (const float*)d_in[5],  *b1  = (const float*)d_in[6];
    const float* W2 = (const float*)d_in[7],  *al2 = (const float*)d_in[8];
    const float* ar2= (const float*)d_in[9],  *b2  = (const float*)d_in[10];
    const float* W3 = (const float*)d_in[11], *al3 = (const float*)d_in[12];
    const float* ar3= (const float*)d_in[13], *b3  = (const float*)d_in[14];
    float* out = (float*)d_out;

    __half2* feath;
    float *h, *feat3;
    int* cnt;
    cudaGetSymbolAddress((void**)&feath, g_feath);
    cudaGetSymbolAddress((void**)&h,     g_h);
    cudaGetSymbolAddress((void**)&feat3, g_feat3);
    cudaGetSymbolAddress((void**)&cnt,   g_cnt);

    const int gEthr = cdiv(N_EDGES, 256 * EPT);
    const int gTile = cdiv(N_NODES, 32);
    const int gDst  = cdiv(N_NODES, WPB);

    // -------- CSR build (graph shared by all 3 layers) --------
    cudaMemsetAsync(cnt, 0, N_NODES * sizeof(int));
    hist_dst<<<gEthr, 256>>>(dst);
    scan_rowptr<<<1, 1024>>>();
    scatter_edges<<<gEthr, 256>>>(src, dst);

    // -------- layer 1 (Fin=9, Fo=64) --------
    gemm_attn<9><<<gTile, 192>>>(feats, W1, al1, ar1, feath);
    agg_big<<<gDst, 32 * WPB>>>(feath, b1, h);

    // -------- layer 2 (Fin=64, Fo=64) --------
    gemm_attn<64><<<gTile, 192>>>(h, W2, al2, ar2, feath);
    agg_big<<<gDst, 32 * WPB>>>(feath, b2, h);

    // -------- layer 3 (Fin=64, Fo=2) --------
    gemm3_attn<<<cdiv(N_NODES, 128), 128>>>(h, W3, al3, ar3);
    agg_small<<<gDst, 32 * WPB>>>(feat3, b3, out);
}

// round 5
// speedup vs baseline: 4.1961x; 1.0014x over previous
#include <cuda_runtime.h>
#include <cuda_fp16.h>
#include <math_constants.h>

#define N_NODES 50000
#define N_EDGES 800000
#define HEADS   3
#define HF      64            // H_FEATS
#define HFO     (HEADS*HF)    // 192
#define NH2     (HFO/2)       // 96 half2 per node row (= 24 float4)
#define NCLS    2
#define HFO3    (HEADS*NCLS)  // 6
#define NEG     0.2f
#define WPB     8             // warps per block for per-dst kernels

// ---------------- scratch (device globals; no allocation allowed) ----------
__device__ __align__(16) __half2 g_feath[N_NODES * NH2];  // fp16 feat [N][96] half2
__device__ __align__(16) float   g_el  [N_NODES * 4];     // el per node (padded float4)
__device__ __align__(16) float   g_er  [N_NODES * 4];     // er per node (padded float4)
__device__ float g_h    [N_NODES * HF];                   // inter-layer node feats (fp32)
__device__ float g_feat3[N_NODES * HFO3];                 // layer-3 feat (fp32)
__device__ int   g_csrs [N_EDGES];                        // src node per CSR slot
__device__ int   g_rowp [N_NODES + 1];                    // CSR row pointers (by dst)
__device__ int   g_cnt  [N_NODES];                        // in-degree histogram
__device__ int   g_wpos [N_NODES];                        // scatter cursors

// ---------------- helpers ---------------------------------------------------
__device__ __forceinline__ float lrelu(float v) { return v > 0.f ? v : NEG * v; }
__device__ __forceinline__ float wred_sum(float v) {
#pragma unroll
    for (int o = 16; o; o >>= 1) v += __shfl_xor_sync(~0u, v, o);
    return v;
}

// ================= CSR build ================================================
__global__ void hist_dst(const int4* __restrict__ dst4) {
    int t = blockIdx.x * blockDim.x + threadIdx.x;
    if (t >= N_EDGES / 4) return;
    int4 d = __ldg(&dst4[t]);
    atomicAdd(&g_cnt[d.x], 1);
    atomicAdd(&g_cnt[d.y], 1);
    atomicAdd(&g_cnt[d.z], 1);
    atomicAdd(&g_cnt[d.w], 1);
}
// single-block exclusive scan over 50K counters (1024 threads, chunked)
__global__ void scan_rowptr() {
    __shared__ int wsum[32];
    __shared__ int s_carry;
    const int lane = threadIdx.x & 31, w = threadIdx.x >> 5;
    if (threadIdx.x == 0) s_carry = 0;
    __syncthreads();
    for (int base = 0; base < N_NODES; base += 1024) {
        int i = base + threadIdx.x;
        int v = (i < N_NODES) ? g_cnt[i] : 0;
        int x = v;
#pragma unroll
        for (int o = 1; o < 32; o <<= 1) {
            int y = __shfl_up_sync(~0u, x, o);
            if (lane >= o) x += y;
        }
        if (lane == 31) wsum[w] = x;
        __syncthreads();
        if (w == 0) {
            int y = wsum[lane];
#pragma unroll
            for (int o = 1; o < 32; o <<= 1) {
                int z = __shfl_up_sync(~0u, y, o);
                if (lane >= o) y += z;
            }
            wsum[lane] = y;
        }
        __syncthreads();
        int excl = x - v + (w > 0 ? wsum[w - 1] : 0) + s_carry;
        if (i < N_NODES) { g_rowp[i] = excl; g_wpos[i] = excl; }
        __syncthreads();
        if (threadIdx.x == 0) s_carry += wsum[31];
        __syncthreads();
    }
    if (threadIdx.x == 0) g_rowp[N_NODES] = s_carry;
}
__global__ void scatter_edges(const int4* __restrict__ src4, const int4* __restrict__ dst4) {
    int t = blockIdx.x * blockDim.x + threadIdx.x;
    if (t >= N_EDGES / 4) return;
    int4 s = __ldg(&src4[t]);
    int4 d = __ldg(&dst4[t]);
    g_csrs[atomicAdd(&g_wpos[d.x], 1)] = s.x;
    g_csrs[atomicAdd(&g_wpos[d.y], 1)] = s.y;
    g_csrs[atomicAdd(&g_wpos[d.z], 1)] = s.z;
    g_csrs[atomicAdd(&g_wpos[d.w], 1)] = s.w;
}

// ================= fused GEMM + attn dots (HFo = 192) =======================
// block: 192 threads = 4 node-groups x 48 col-groups; thread: 8 nodes x 4 cols.
template <int FIN>
__global__ void gemm_attn(const float* __restrict__ x,
                          const float* __restrict__ W,
                          const float* __restrict__ al,
                          const float* __restrict__ ar,
                          __half2* __restrict__ feath) {
    __shared__ float xs[32 * FIN];
    const int tid = threadIdx.x;
    const int cg  = tid % 48;
    const int ng  = tid / 48;
    const int n0  = blockIdx.x * 32;
    const int head = cg / 16;
    const int c64  = (cg % 16) * 4;

    for (int i = tid; i < 32 * FIN; i += 192) {
        int node = n0 + i / FIN;
        xs[i] = (node < N_NODES) ? x[node * FIN + i % FIN] : 0.f;
    }
    __syncthreads();

    float acc[8][4];
#pragma unroll
    for (int i = 0; i < 8; i++)
#pragma unroll
        for (int j = 0; j < 4; j++) acc[i][j] = 0.f;

    const float* xb = xs + ng * 8 * FIN;
    for (int k = 0; k < FIN; k++) {
        float4 w = __ldg(reinterpret_cast<const float4*>(W + k * HFO + cg * 4));
#pragma unroll
        for (int i = 0; i < 8; i++) {
            float xv = xb[i * FIN + k];
            acc[i][0] += xv * w.x;
            acc[i][1] += xv * w.y;
            acc[i][2] += xv * w.z;
            acc[i][3] += xv * w.w;
        }
    }

#pragma unroll
    for (int i = 0; i < 8; i++) {
        int node = n0 + ng * 8 + i;
        if (node < N_NODES) {
            feath[node * NH2 + cg * 2]     = __floats2half2_rn(acc[i][0], acc[i][1]);
            feath[node * NH2 + cg * 2 + 1] = __floats2half2_rn(acc[i][2], acc[i][3]);
        }
    }

    float a0 = __ldg(&al[head * HF + c64 + 0]), a1 = __ldg(&al[head * HF + c64 + 1]);
    float a2 = __ldg(&al[head * HF + c64 + 2]), a3 = __ldg(&al[head * HF + c64 + 3]);
    float r0 = __ldg(&ar[head * HF + c64 + 0]), r1 = __ldg(&ar[head * HF + c64 + 1]);
    float r2 = __ldg(&ar[head * HF + c64 + 2]), r3 = __ldg(&ar[head * HF + c64 + 3]);
#pragma unroll
    for (int i = 0; i < 8; i++) {
        float sl = acc[i][0]*a0 + acc[i][1]*a1 + acc[i][2]*a2 + acc[i][3]*a3;
        float sr = acc[i][0]*r0 + acc[i][1]*r1 + acc[i][2]*r2 + acc[i][3]*r3;
#pragma unroll
        for (int o = 8; o; o >>= 1) {
            sl += __shfl_down_sync(~0u, sl, o, 16);
            sr += __shfl_down_sync(~0u, sr, o, 16);
        }
        if ((tid & 15) == 0) {
            int node = n0 + ng * 8 + i;
            if (node < N_NODES) {
                g_el[node * 4 + head] = sl;
                g_er[node * 4 + head] = sr;
            }
        }
    }
}

// ================= fused layer-3 GEMM + attn dots (HFo = 6) =================
__global__ void gemm3_attn(const float* __restrict__ x,
                           const float* __restrict__ W,
                           const float* __restrict__ al,
                           const float* __restrict__ ar) {
    int n = blockIdx.x * blockDim.x + threadIdx.x;
    if (n >= N_NODES) return;
    float acc[HFO3];
#pragma unroll
    for (int c = 0; c < HFO3; c++) acc[c] = 0.f;
    const float4* xr = reinterpret_cast<const float4*>(x + n * HF);
    for (int k4 = 0; k4 < HF / 4; k4++) {
        float4 xv = __ldg(xr + k4);
#pragma unroll
        for (int c = 0; c < HFO3; c++) {
            acc[c] += xv.x * __ldg(&W[(k4*4+0) * HFO3 + c]);
            acc[c] += xv.y * __ldg(&W[(k4*4+1) * HFO3 + c]);
            acc[c] += xv.z * __ldg(&W[(k4*4+2) * HFO3 + c]);
            acc[c] += xv.w * __ldg(&W[(k4*4+3) * HFO3 + c]);
        }
    }
#pragma unroll
    for (int c = 0; c < HFO3; c++) g_feat3[n * HFO3 + c] = acc[c];
#pragma unroll
    for (int h = 0; h < HEADS; h++) {
        g_el[n * 4 + h] = acc[h*NCLS+0] * __ldg(&al[h*NCLS+0]) + acc[h*NCLS+1] * __ldg(&al[h*NCLS+1]);
        g_er[n * 4 + h] = acc[h*NCLS+0] * __ldg(&ar[h*NCLS+0]) + acc[h*NCLS+1] * __ldg(&ar[h*NCLS+1]);
    }
}

// ================= fused softmax + aggregation, Fo = 64, fp16 gather ========
// one warp per dst. Per 32-edge chunk: all lanes compute (src, weights), stage
// in smem; then 24 lanes gather the 384B row as one float4 each (head = lane>>3),
// accumulating 8 fp32. Epilogue: head-sum via shfl_down(8,16), lanes 0-7 store.
__global__ void agg_big(const __half2* __restrict__ feath,
                        const float* __restrict__ bias,
                        float* __restrict__ out) {
    __shared__ int   s_src[WPB][32];
    __shared__ float s_w[WPB][3][32];
    const int lane = threadIdx.x & 31;
    const int wrp  = threadIdx.x >> 5;
    const int d = blockIdx.x * WPB + wrp;
    if (d >= N_NODES) return;
    const int beg = g_rowp[d], end = g_rowp[d + 1];
    const int head = lane >> 3;          // valid for lane < 24

    const float4 er = *reinterpret_cast<const float4*>(g_er + 4 * d);
    float s0 = 0.f, s1 = 0.f, s2 = 0.f;
    float acc[8];
#pragma unroll
    for (int k = 0; k < 8; k++) acc[k] = 0.f;

    for (int base = beg; base < end; base += 32) {
        int i = base + lane;
        int   sl  = 0;
        float w0l = 0.f, w1l = 0.f, w2l = 0.f;
        if (i < end) {
            sl = __ldg(&g_csrs[i]);
            float4 e = *reinterpret_cast<const float4*>(g_el + 4 * sl);
            w0l = __expf(lrelu(e.x + er.x));
            w1l = __expf(lrelu(e.y + er.y));
            w2l = __expf(lrelu(e.z + er.z));
        }
        s0 += w0l; s1 += w1l; s2 += w2l;
        s_src[wrp][lane] = sl;
        s_w[wrp][0][lane] = w0l;
        s_w[wrp][1][lane] = w1l;
        s_w[wrp][2][lane] = w2l;
        __syncwarp();
        const int cnt = min(32, end - base);
        if (lane < 24) {
            for (int j = 0; j < cnt; j++) {
                const int   s = s_src[wrp][j];            // LDS broadcast
                const float w = s_w[wrp][head][j];        // LDS broadcast
                const float4* fp4 = reinterpret_cast<const float4*>(feath + s * NH2);
                float4 v = __ldg(fp4 + lane);             // one LDG.128 per lane
                const __half2* hv = reinterpret_cast<const __half2*>(&v);
                float2 f0 = __half22float2(hv[0]);
                float2 f1 = __half22float2(hv[1]);
                float2 f2 = __half22float2(hv[2]);
                float2 f3 = __half22float2(hv[3]);
                acc[0] += w * f0.x;  acc[1] += w * f0.y;
                acc[2] += w * f1.x;  acc[3] += w * f1.y;
                acc[4] += w * f2.x;  acc[5] += w * f2.y;
                acc[6] += w * f3.x;  acc[7] += w * f3.y;
            }
        }
        __syncwarp();
    }
    s0 = wred_sum(s0); s1 = wred_sum(s1); s2 = wred_sum(s2);
    const float i0 = s0 > 0.f ? 1.f / s0 : 0.f;
    const float i1 = s1 > 0.f ? 1.f / s1 : 0.f;
    const float i2 = s2 > 0.f ? 1.f / s2 : 0.f;
    const float inv = (head == 0) ? i0 : (head == 1) ? i1 : i2;
#pragma unroll
    for (int k = 0; k < 8; k++) acc[k] *= inv;

    // head-sum: lane m (<8) += lane m+8 and lane m+16 (cols 8m+k)
#pragma unroll
    for (int k = 0; k < 8; k++) {
        float v8  = __shfl_down_sync(~0u, acc[k], 8);
        float v16 = __shfl_down_sync(~0u, acc[k], 16);
        acc[k] += v8 + v16;
    }
    if (lane < 8) {
        const int c = 8 * lane;
#pragma unroll
        for (int k = 0; k < 8; k++)
            acc[k] += __ldg(&bias[c + k]) + __ldg(&bias[HF + c + k]) + __ldg(&bias[2*HF + c + k]);
        float4 o0 = make_float4(acc[0], acc[1], acc[2], acc[3]);
        float4 o1 = make_float4(acc[4], acc[5], acc[6], acc[7]);
        *reinterpret_cast<float4*>(out + d * HF + c)     = o0;
        *reinterpret_cast<float4*>(out + d * HF + c + 4) = o1;
    }
}

// ================= fused softmax + aggregation, Fo = 2 (layer 3) ============
__global__ void agg_small(const float* __restrict__ feat,
                          const float* __restrict__ bias,
                          float* __restrict__ out) {
    const int lane = threadIdx.x & 31;
    const int d = blockIdx.x * WPB + (threadIdx.x >> 5);
    if (d >= N_NODES) return;
    const int beg = g_rowp[d], end = g_rowp[d + 1];
    const float4 er = *reinterpret_cast<const float4*>(g_er + 4 * d);

    float s0 = 0.f, s1 = 0.f, s2 = 0.f;
    float c00 = 0.f, c01 = 0.f, c10 = 0.f, c11 = 0.f, c20 = 0.f, c21 = 0.f;
    for (int i = beg + lane; i < end; i += 32) {
        int s = __ldg(&g_csrs[i]);
        float4 e = *reinterpret_cast<const float4*>(g_el + 4 * s);
        float w0 = __expf(lrelu(e.x + er.x));
        float w1 = __expf(lrelu(e.y + er.y));
        float w2 = __expf(lrelu(e.z + er.z));
        s0 += w0; s1 += w1; s2 += w2;
        const float* fp = feat + s * HFO3;
        c00 += w0 * __ldg(fp + 0); c01 += w0 * __ldg(fp + 1);
        c10 += w1 * __ldg(fp + 2); c11 += w1 * __ldg(fp + 3);
        c20 += w2 * __ldg(fp + 4); c21 += w2 * __ldg(fp + 5);
    }
    s0 = wred_sum(s0); s1 = wred_sum(s1); s2 = wred_sum(s2);
    c00 = wred_sum(c00); c01 = wred_sum(c01);
    c10 = wred_sum(c10); c11 = wred_sum(c11);
    c20 = wred_sum(c20); c21 = wred_sum(c21);
    if (lane == 0) {
        const float i0 = s0 > 0.f ? 1.f / s0 : 0.f;
        const float i1 = s1 > 0.f ? 1.f / s1 : 0.f;
        const float i2 = s2 > 0.f ? 1.f / s2 : 0.f;
        float b0 = __ldg(&bias[0]) + __ldg(&bias[2]) + __ldg(&bias[4]);
        float b1 = __ldg(&bias[1]) + __ldg(&bias[3]) + __ldg(&bias[5]);
        out[d * NCLS + 0] = c00 * i0 + c10 * i1 + c20 * i2 + b0;
        out[d * NCLS + 1] = c01 * i0 + c11 * i1 + c21 * i2 + b1;
    }
}

// ================= host driver ==============================================
static inline int cdiv(int a, int b) { return (a + b - 1) / b; }

extern "C" void kernel_launch(void* const* d_in, const int* in_sizes, int n_in,
                              void* d_out, int out_size) {
    const float* feats = (const float*)d_in[0];
    const int*   src   = (const int*)  d_in[1];
    const int*   dst   = (const int*)  d_in[2];
    const float* W1 = (const float*)d_in[3],  *al1 = (const float*)d_in[4];
    const float* ar1= (const float*)d_in[5],  *b1  = (const float*)d_in[6];
    const float* W2 = (const float*)d_in[7],  *al2 = (const float*)d_in[8];
    const float* ar2= (const float*)d_in[9],  *b2  = (const float*)d_in[10];
    const float* W3 = (const float*)d_in[11], *al3 = (const float*)d_in[12];
    const float* ar3= (const float*)d_in[13], *b3  = (const float*)d_in[14];
    float* out = (float*)d_out;

    __half2* feath;
    float *h;
    float *feat3;
    int* cnt;
    cudaGetSymbolAddress((void**)&feath, g_feath);
    cudaGetSymbolAddress((void**)&h,     g_h);
    cudaGetSymbolAddress((void**)&feat3, g_feat3);
    cudaGetSymbolAddress((void**)&cnt,   g_cnt);

    const int gE4   = cdiv(N_EDGES / 4, 256);
    const int gTile = cdiv(N_NODES, 32);
    const int gDst  = cdiv(N_NODES, WPB);

    // -------- CSR build (graph shared by all 3 layers) --------
    cudaMemsetAsync(cnt, 0, N_NODES * sizeof(int));
    hist_dst<<<gE4, 256>>>((const int4*)dst);
    scan_rowptr<<<1, 1024>>>();
    scatter_edges<<<gE4, 256>>>((const int4*)src, (const int4*)dst);

    // -------- layer 1 (Fin=9, Fo=64) --------
    gemm_attn<9><<<gTile, 192>>>(feats, W1, al1, ar1, feath);
    agg_big<<<gDst, 32 * WPB>>>(feath, b1, h);

    // -------- layer 2 (Fin=64, Fo=64) --------
    gemm_attn<64><<<gTile, 192>>>(h, W2, al2, ar2, feath);
    agg_big<<<gDst, 32 * WPB>>>(feath, b2, h);

    // -------- layer 3 (Fin=64, Fo=2) --------
    gemm3_attn<<<cdiv(N_NODES, 128), 128>>>(h, W3, al3, ar3);
    agg_small<<<gDst, 32 * WPB>>>(feat3, b3, out);
}